// round 1
// baseline (speedup 1.0000x reference)
#include <cuda_runtime.h>

#define W_DIM 1024
#define F_DIM 512
#define NHD   64          // head dim
#define NBC   8           // B*C
#define QK_SCALE 0.044194173824159216f  // 1/sqrt(512)

// Scratch (16 MB each) — __device__ globals per allocation rules.
__device__ float g_P[NBC * F_DIM * W_DIM];  // projection (also V source)
__device__ float g_Q[NBC * F_DIM * W_DIM];  // roped Q (== roped K)
__device__ float g_A[NBC * F_DIM * W_DIM];  // attention output

// ---------------------------------------------------------------------------
// GEMM: Out[bc][g][w] = sum_h Wm[c][g][h] * X[bc][h][w]
// BM=BN=128, BK=16, 256 threads, 8x8 micro-tile.
// Xin==nullptr -> read g_A ; Oin==nullptr -> write g_P.
// ---------------------------------------------------------------------------
__global__ __launch_bounds__(256) void gemm_kernel(const float* __restrict__ Wm,
                                                   const float* __restrict__ Xin,
                                                   float* __restrict__ Oin) {
    __shared__ float As[16 * 132];  // [kk][m], padded row 132 (528B, 16B-aligned)
    __shared__ float Bs[16 * 128];  // [kk][n]

    const float* X = Xin ? Xin : g_A;
    float*       O = Oin ? Oin : g_P;

    const int bc = blockIdx.z;
    const float* Wb = Wm + (size_t)(bc & 1) * F_DIM * F_DIM;
    const float* Xb = X  + (size_t)bc * F_DIM * W_DIM;
    float*       Ob = O  + (size_t)bc * F_DIM * W_DIM;

    const int g0 = blockIdx.y * 128;
    const int w0 = blockIdx.x * 128;

    const int tid = threadIdx.x;
    const int ty = tid >> 4, tx = tid & 15;   // 16x16 thread grid
    const int lw = tid & 3,  lg = tid >> 2;   // A-tile load mapping
    const int lk = tid >> 4, lx = tid & 15;   // B-tile load mapping

    float acc[8][8];
#pragma unroll
    for (int i = 0; i < 8; i++)
#pragma unroll
        for (int j = 0; j < 8; j++) acc[i][j] = 0.f;

    for (int k0 = 0; k0 < F_DIM; k0 += 16) {
        __syncthreads();
        // Load A tile (W matrix): rows g, cols h -> As[kk][g]
#pragma unroll
        for (int r = 0; r < 128; r += 64) {
            float4 v = *(const float4*)&Wb[(size_t)(g0 + lg + r) * F_DIM + k0 + lw * 4];
            As[(lw * 4 + 0) * 132 + lg + r] = v.x;
            As[(lw * 4 + 1) * 132 + lg + r] = v.y;
            As[(lw * 4 + 2) * 132 + lg + r] = v.z;
            As[(lw * 4 + 3) * 132 + lg + r] = v.w;
        }
        // Load B tile (X): rows h, cols w -> Bs[kk][w]
#pragma unroll
        for (int r = 0; r < 128; r += 64) {
            *(float4*)&Bs[lk * 128 + lx * 4 + r] =
                *(const float4*)&Xb[(size_t)(k0 + lk) * W_DIM + w0 + lx * 4 + r];
        }
        __syncthreads();
#pragma unroll
        for (int kk = 0; kk < 16; kk++) {
            float a[8], b[8];
            *(float4*)&a[0] = *(float4*)&As[kk * 132 + ty * 8];
            *(float4*)&a[4] = *(float4*)&As[kk * 132 + ty * 8 + 4];
            *(float4*)&b[0] = *(float4*)&Bs[kk * 128 + tx * 8];
            *(float4*)&b[4] = *(float4*)&Bs[kk * 128 + tx * 8 + 4];
#pragma unroll
            for (int i = 0; i < 8; i++)
#pragma unroll
                for (int j = 0; j < 8; j++) acc[i][j] += a[i] * b[j];
        }
    }
#pragma unroll
    for (int i = 0; i < 8; i++) {
        float* dst = &Ob[(size_t)(g0 + ty * 8 + i) * W_DIM + w0 + tx * 8];
        *(float4*)dst       = make_float4(acc[i][0], acc[i][1], acc[i][2], acc[i][3]);
        *(float4*)(dst + 4) = make_float4(acc[i][4], acc[i][5], acc[i][6], acc[i][7]);
    }
}

// ---------------------------------------------------------------------------
// RoPE: interleaved pairs on first 32 dims of each 64-dim head.
// g_Q[bc][g][w]: for hd<32, j=hd/2, theta=w*fp[j]:
//   even: p0*cos - p1*sin ; odd: p0*cos + p(-1)*sin ; hd>=32 passthrough.
// ---------------------------------------------------------------------------
__global__ __launch_bounds__(256) void rope_kernel(const float* __restrict__ fp) {
    int idx = blockIdx.x * 256 + threadIdx.x;   // [bc][g][w] linear
    int w  = idx & (W_DIM - 1);
    int g  = (idx >> 10) & (F_DIM - 1);
    int hd = g & (NHD - 1);
    float p0 = g_P[idx];
    float val;
    if (hd < 32) {
        int j = hd >> 1;
        float th = (float)w * fp[j];
        float s, c;
        sincosf(th, &s, &c);            // accurate range reduction (theta up to ~1.6e4)
        if ((hd & 1) == 0) {
            float p1 = g_P[idx + W_DIM];
            val = p0 * c - p1 * s;
        } else {
            float pm = g_P[idx - W_DIM];
            val = p0 * c + pm * s;
        }
    } else {
        val = p0;
    }
    g_Q[idx] = val;
}

// ---------------------------------------------------------------------------
// Flash attention, fp32, online softmax. K == Q (both read g_Q), V from g_P.
// Block: 64 queries x full key sweep in 64-key tiles. 256 threads, 4x4 micro.
// grid = (16 q-tiles, 64 heads). Dynamic smem = 67328 B.
// ---------------------------------------------------------------------------
__global__ __launch_bounds__(256) void attn_kernel() {
    extern __shared__ float sm[];
    float* Qs   = sm;             // [64][64] layout (d, q)
    float* Ks   = sm + 4096;      // [64][64] layout (d, k)
    float* Vs   = sm + 8192;      // [64][64] layout (k, d) XOR-swizzled 16B granules
    float* Ss   = sm + 12288;     // [64][68] layout (k, q), row pad 68 (272B aligned)
    float* Mrow = sm + 16640;     // [64]
    float* Lrow = sm + 16704;     // [64]
    float* Arow = sm + 16768;     // [64]

    const int tid = threadIdx.x;
    const int q0  = blockIdx.x * 64;
    const int bcn = blockIdx.y;   // bc*8 + n, matches g = n*64+d layout directly

    const float* Qb = g_Q + (size_t)bcn * (NHD * W_DIM);
    const float* Vb = g_P + (size_t)bcn * (NHD * W_DIM);
    float*       Ab = g_A + (size_t)bcn * (NHD * W_DIM);

    // Load Q tile (scaled by 1/sqrt(F)); layout (d, q)
    for (int i = tid; i < 4096; i += 256) {
        int d = i >> 6, q = i & 63;
        Qs[i] = Qb[(size_t)d * W_DIM + q0 + q] * QK_SCALE;
    }
    if (tid < 64) { Mrow[tid] = -1e30f; Lrow[tid] = 0.f; }

    const int ty = tid >> 4, tx = tid & 15;     // micro-tile owner: q-group ty, k/d-group tx
    const int qq = tid >> 2, sub = tid & 3;     // softmax mapping: 4 lanes per query row
    float o[4][4];
#pragma unroll
    for (int i = 0; i < 4; i++)
#pragma unroll
        for (int j = 0; j < 4; j++) o[i][j] = 0.f;

    for (int kt = 0; kt < 16; kt++) {
        const int k0 = kt * 64;
        __syncthreads();   // protect previous-iteration reads of Ks/Vs/Ss
        for (int i = tid; i < 4096; i += 256) {
            int d = i >> 6, k = i & 63;
            Ks[i] = Qb[(size_t)d * W_DIM + k0 + k];                    // K == roped Q
            float vv = Vb[(size_t)d * W_DIM + k0 + k];
            Vs[(k << 6) + ((((d >> 2) ^ (k & 15)) << 2) | (d & 3))] = vv;  // swizzled transpose
        }
        __syncthreads();

        // --- scores: s[qi][kj] = sum_d Q[d][q]*K[d][k] ---
        float s[4][4];
#pragma unroll
        for (int i = 0; i < 4; i++)
#pragma unroll
            for (int j = 0; j < 4; j++) s[i][j] = 0.f;
#pragma unroll
        for (int d = 0; d < 64; d++) {
            float a[4], b[4];
            *(float4*)a = *(float4*)&Qs[(d << 6) + (ty << 2)];
            *(float4*)b = *(float4*)&Ks[(d << 6) + (tx << 2)];
#pragma unroll
            for (int i = 0; i < 4; i++)
#pragma unroll
                for (int j = 0; j < 4; j++) s[i][j] += a[i] * b[j];
        }
#pragma unroll
        for (int j = 0; j < 4; j++) {   // Ss[k][q], float4 along q
            *(float4*)&Ss[(tx * 4 + j) * 68 + ty * 4] =
                make_float4(s[0][j], s[1][j], s[2][j], s[3][j]);
        }
        __syncthreads();

        // --- online softmax update (4 lanes cooperate per query) ---
        float mx = -1e30f;
#pragma unroll
        for (int ki = sub; ki < 64; ki += 4) mx = fmaxf(mx, Ss[ki * 68 + qq]);
        mx = fmaxf(mx, __shfl_xor_sync(0xffffffffu, mx, 1));
        mx = fmaxf(mx, __shfl_xor_sync(0xffffffffu, mx, 2));
        float m_old = Mrow[qq];
        float m_new = fmaxf(m_old, mx);
        float ssum = 0.f;
#pragma unroll
        for (int ki = sub; ki < 64; ki += 4) {
            float p = __expf(Ss[ki * 68 + qq] - m_new);
            Ss[ki * 68 + qq] = p;
            ssum += p;
        }
        ssum += __shfl_xor_sync(0xffffffffu, ssum, 1);
        ssum += __shfl_xor_sync(0xffffffffu, ssum, 2);
        if (sub == 0) {
            float al = __expf(m_old - m_new);
            Arow[qq] = al;
            Lrow[qq] = Lrow[qq] * al + ssum;
            Mrow[qq] = m_new;
        }
        __syncthreads();

        // --- rescale + PV accumulate ---
        float al0 = Arow[ty * 4 + 0], al1 = Arow[ty * 4 + 1];
        float al2 = Arow[ty * 4 + 2], al3 = Arow[ty * 4 + 3];
#pragma unroll
        for (int j = 0; j < 4; j++) {
            o[0][j] *= al0; o[1][j] *= al1; o[2][j] *= al2; o[3][j] *= al3;
        }
#pragma unroll
        for (int ki = 0; ki < 64; ki++) {
            float a[4], b[4];
            *(float4*)a = *(float4*)&Ss[ki * 68 + ty * 4];                       // p[k][q]
            *(float4*)b = *(float4*)&Vs[(ki << 6) + ((tx ^ (ki & 15)) << 2)];    // V[k][d]
#pragma unroll
            for (int i = 0; i < 4; i++)
#pragma unroll
                for (int j = 0; j < 4; j++) o[i][j] += a[i] * b[j];
        }
    }

    __syncthreads();  // last PV reads of Ss done; safe to reuse for staging
    float inv0 = 1.f / Lrow[ty * 4 + 0];
    float inv1 = 1.f / Lrow[ty * 4 + 1];
    float inv2 = 1.f / Lrow[ty * 4 + 2];
    float inv3 = 1.f / Lrow[ty * 4 + 3];
#pragma unroll
    for (int j = 0; j < 4; j++) {   // stage as (d, q) into Ss
        *(float4*)&Ss[(tx * 4 + j) * 68 + ty * 4] =
            make_float4(o[0][j] * inv0, o[1][j] * inv1, o[2][j] * inv2, o[3][j] * inv3);
    }
    __syncthreads();
    for (int i = tid; i < 4096; i += 256) {
        int d = i >> 6, q = i & 63;
        Ab[(size_t)d * W_DIM + q0 + q] = Ss[d * 68 + q];
    }
}

// ---------------------------------------------------------------------------
// Launch. Inputs (metadata order): x, wq, wk, wv, wo, freqs_param.
// wk/wv are unused by the reference (it uses wq for q, k AND v).
// ---------------------------------------------------------------------------
extern "C" void kernel_launch(void* const* d_in, const int* in_sizes, int n_in,
                              void* d_out, int out_size) {
    (void)in_sizes; (void)n_in; (void)out_size;
    const float* x  = (const float*)d_in[0];
    const float* wq = (const float*)d_in[1];
    const float* wo = (const float*)d_in[4];
    const float* fp = (const float*)d_in[5];
    float* out = (float*)d_out;

    cudaFuncSetAttribute(attn_kernel, cudaFuncAttributeMaxDynamicSharedMemorySize, 67328);

    dim3 gg(8, 4, 8);                       // (W/128, F/128, B*C)
    gemm_kernel<<<gg, 256>>>(wq, x, nullptr);        // P = Wq @ X
    rope_kernel<<<16384, 256>>>(fp);                 // Q = rope(P)
    attn_kernel<<<dim3(16, 64), 256, 67328>>>();     // A = softmax(QQ^T/√F) V
    gemm_kernel<<<gg, 256>>>(wo, nullptr, out);      // out = Wo @ A
}